// round 8
// baseline (speedup 1.0000x reference)
#include <cuda_runtime.h>
#include <cuda_bf16.h>
#include <cstdint>

// ---------------------------------------------------------------------------
// GraphSAGE on GB300, round 7:
//  - CSR pull-mode mean aggregation, tf32 mma.sync GEMMs (as round 4)
//  - NEW: dual-stream fork/join inside graph capture:
//      * CSR build overlaps prep + layer-0 self-GEMM
//      * layer-1 self-GEMM overlaps layer-1 pull
//    Each layer split: S = h@wr^T + b  (self)   [K=128 GEMM]
//                      h' = relu(mean@wl^T + S) * dropout  [K=128 GEMM]
// ---------------------------------------------------------------------------

constexpr int   NN   = 50000;
constexpr int   EE   = 800000;
constexpr int   D    = 128;
constexpr int   DO   = 64;
constexpr float PDROP = 0.3f;
constexpr float INV_KEEP = 1.0f / 0.7f;

constexpr int SCAN_B = 256;
constexpr int SCAN_NBLK = (NN + SCAN_B - 1) / SCAN_B;   // 196

// ---- scratch (static device globals) ----
__device__ __align__(256) float g_agg[NN * D];
__device__ __align__(256) float g_s  [NN * D];     // self-term buffer (reused per layer)
__device__ __align__(256) float g_h0 [NN * D];
__device__ __align__(256) float g_h1 [NN * D];
__device__ __align__(256) float g_y  [NN * DO];
__device__ __align__(256) float g_wT [5 * D * D];
__device__ __align__(256) int   g_deg[NN];
__device__ __align__(256) int   g_rowptr[NN + 1];
__device__ __align__(256) int   g_cursor[NN];
__device__ __align__(256) int   g_adj[EE];
__device__ __align__(256) int   g_blksum[SCAN_NBLK + 1];

// ---------------------------------------------------------------------------
__global__ void prep_weights(const float* __restrict__ wl0, const float* __restrict__ wr0,
                             const float* __restrict__ wl1, const float* __restrict__ wr1,
                             const float* __restrict__ wl2, const float* __restrict__ wr2) {
    int idx = blockIdx.x * blockDim.x + threadIdx.x;
    if (idx >= 5 * D * D) return;
    int seg = idx / (D * D);
    int r   = idx % (D * D);
    int k = r / D, n = r % D;
    float v;
    switch (seg) {
        case 0:  v = wl0[n * D + k]; break;
        case 1:  v = wr0[n * D + k]; break;
        case 2:  v = wl1[n * D + k]; break;
        case 3:  v = wr1[n * D + k]; break;
        default: v = (n < DO) ? wl2[n * D + k] : wr2[(n - DO) * D + k]; break;
    }
    g_wT[idx] = v;
}

__global__ void zero_deg() {
    int i = blockIdx.x * blockDim.x + threadIdx.x;
    if (i < NN) g_deg[i] = 0;
}

__global__ void deg_kernel(const int* __restrict__ ei) {
    int e = blockIdx.x * blockDim.x + threadIdx.x;
    if (e < EE) atomicAdd(&g_deg[ei[EE + e]], 1);
}

__global__ void scan_s1() {
    __shared__ int sh[SCAN_B];
    int idx = blockIdx.x * SCAN_B + threadIdx.x;
    int v = (idx < NN) ? g_deg[idx] : 0;
    sh[threadIdx.x] = v;
    __syncthreads();
    for (int off = SCAN_B / 2; off > 0; off >>= 1) {
        if (threadIdx.x < off) sh[threadIdx.x] += sh[threadIdx.x + off];
        __syncthreads();
    }
    if (threadIdx.x == 0) g_blksum[blockIdx.x] = sh[0];
}

__global__ void scan_s2() {
    __shared__ int sh[SCAN_NBLK];
    int t = threadIdx.x;
    if (t < SCAN_NBLK) sh[t] = g_blksum[t];
    __syncthreads();
    for (int off = 1; off < SCAN_NBLK; off <<= 1) {
        int v = 0;
        if (t < SCAN_NBLK && t >= off) v = sh[t - off];
        __syncthreads();
        if (t < SCAN_NBLK && t >= off) sh[t] += v;
        __syncthreads();
    }
    if (t < SCAN_NBLK) g_blksum[t] = (t > 0) ? sh[t - 1] : 0;
    if (t == SCAN_NBLK - 1) {
        g_blksum[SCAN_NBLK] = sh[SCAN_NBLK - 1];
        g_rowptr[NN] = sh[SCAN_NBLK - 1];
    }
}

__global__ void scan_s3() {
    __shared__ int sh[SCAN_B];
    int idx = blockIdx.x * SCAN_B + threadIdx.x;
    int t = threadIdx.x;
    int v = (idx < NN) ? g_deg[idx] : 0;
    sh[t] = v;
    __syncthreads();
    for (int off = 1; off < SCAN_B; off <<= 1) {
        int p = 0;
        if (t >= off) p = sh[t - off];
        __syncthreads();
        if (t >= off) sh[t] += p;
        __syncthreads();
    }
    if (idx < NN) {
        int ex = sh[t] - v + g_blksum[blockIdx.x];
        g_rowptr[idx] = ex;
        g_cursor[idx] = ex;
    }
}

__global__ void fill_kernel(const int* __restrict__ ei) {
    int e = blockIdx.x * blockDim.x + threadIdx.x;
    if (e < EE) {
        int d = ei[EE + e];
        int pos = atomicAdd(&g_cursor[d], 1);
        g_adj[pos] = ei[e];
    }
}

// ---------------------------------------------------------------------------
// Pull-mode mean, 128-d: one warp per node, one float4 per lane.
// ---------------------------------------------------------------------------
__global__ void pull128_kernel(const float4* __restrict__ feat, float4* __restrict__ out) {
    int warp = (blockIdx.x * blockDim.x + threadIdx.x) >> 5;
    int lane = threadIdx.x & 31;
    if (warp >= NN) return;
    int beg = g_rowptr[warp], end = g_rowptr[warp + 1];
    float4 a0 = make_float4(0.f, 0.f, 0.f, 0.f);
    float4 a1 = make_float4(0.f, 0.f, 0.f, 0.f);
    for (int eb = beg; eb < end; eb += 32) {
        int n = end - eb;
        int myAdj = (lane < n) ? __ldg(&g_adj[eb + lane]) : 0;
        int lim = min(n, 32);
        int t = 0;
        for (; t + 2 <= lim; t += 2) {
            int s0 = __shfl_sync(0xffffffffu, myAdj, t);
            int s1 = __shfl_sync(0xffffffffu, myAdj, t + 1);
            float4 v0 = __ldg(&feat[(size_t)s0 * 32 + lane]);
            float4 v1 = __ldg(&feat[(size_t)s1 * 32 + lane]);
            a0.x += v0.x; a0.y += v0.y; a0.z += v0.z; a0.w += v0.w;
            a1.x += v1.x; a1.y += v1.y; a1.z += v1.z; a1.w += v1.w;
        }
        if (t < lim) {
            int s0 = __shfl_sync(0xffffffffu, myAdj, t);
            float4 v0 = __ldg(&feat[(size_t)s0 * 32 + lane]);
            a0.x += v0.x; a0.y += v0.y; a0.z += v0.z; a0.w += v0.w;
        }
    }
    float sc = 1.0f / fmaxf((float)(end - beg), 1.0f);
    a0.x = (a0.x + a1.x) * sc; a0.y = (a0.y + a1.y) * sc;
    a0.z = (a0.z + a1.z) * sc; a0.w = (a0.w + a1.w) * sc;
    out[(size_t)warp * 32 + lane] = a0;
}

// Pull-mode mean, 64-d, accumulating into out (+=). Half-warp per node.
__global__ void pull64_add_kernel(const float4* __restrict__ feat, float4* __restrict__ out) {
    int gid = blockIdx.x * blockDim.x + threadIdx.x;
    int node = gid >> 4;
    int c = gid & 15;
    if (node >= NN) return;
    int beg = g_rowptr[node], end = g_rowptr[node + 1];
    float4 a0 = make_float4(0.f, 0.f, 0.f, 0.f);
    float4 a1 = make_float4(0.f, 0.f, 0.f, 0.f);
    for (int eb = beg; eb < end; eb += 16) {
        int n = end - eb;
        int myAdj = (c < n) ? __ldg(&g_adj[eb + c]) : 0;
        int lim = min(n, 16);
        int t = 0;
        for (; t + 2 <= lim; t += 2) {
            int s0 = __shfl_sync(0xffffffffu, myAdj, t, 16);
            int s1 = __shfl_sync(0xffffffffu, myAdj, t + 1, 16);
            float4 v0 = __ldg(&feat[(size_t)s0 * 16 + c]);
            float4 v1 = __ldg(&feat[(size_t)s1 * 16 + c]);
            a0.x += v0.x; a0.y += v0.y; a0.z += v0.z; a0.w += v0.w;
            a1.x += v1.x; a1.y += v1.y; a1.z += v1.z; a1.w += v1.w;
        }
        if (t < lim) {
            int s0 = __shfl_sync(0xffffffffu, myAdj, t, 16);
            float4 v0 = __ldg(&feat[(size_t)s0 * 16 + c]);
            a0.x += v0.x; a0.y += v0.y; a0.z += v0.z; a0.w += v0.w;
        }
    }
    float sc = 1.0f / fmaxf((float)(end - beg), 1.0f);
    float4 o = out[(size_t)node * 16 + c];
    o.x += (a0.x + a1.x) * sc; o.y += (a0.y + a1.y) * sc;
    o.z += (a0.z + a1.z) * sc; o.w += (a0.w + a1.w) * sc;
    out[(size_t)node * 16 + c] = o;
}

// ---------------------------------------------------------------------------
// tf32 tensor-core GEMM, K=128, N=128.
// MODE 0 (self):  out1 = A1 @ WT + bias
// MODE 1 (mean):  out1 = relu( A1 @ WT + S ) * dropout(u)
// MODE 2 (lyr2):  cols 0..63 -> out1 = A1 @ wl2^T ; cols 64..127 -> out2 = A1 @ wr2^T + bias
// ---------------------------------------------------------------------------
__device__ __forceinline__ uint32_t f2tf32(float f) {
    uint32_t r;
    asm("cvt.rna.tf32.f32 %0, %1;" : "=r"(r) : "f"(f));
    return r;
}

template <int MODE>
__launch_bounds__(256)
__global__ void gemm_tf32(const float* __restrict__ A1, const float* __restrict__ WT,
                          const float* __restrict__ bias, const float* __restrict__ S,
                          const float* __restrict__ u,
                          float* __restrict__ out1, float* __restrict__ out2) {
    constexpr int BM = 128, BN = 128, BK = 32;
    constexpr int KT = 128;
    __shared__ uint32_t As[BM][BK + 4];
    __shared__ uint32_t Ws[BK][BN + 8];

    const int tid  = threadIdx.x;
    const int wid  = tid >> 5;
    const int lane = tid & 31;
    const int gidq = lane >> 2;
    const int tg   = lane & 3;
    const int rowBase = (wid >> 2) * 64;
    const int colBase = (wid & 3) * 32;
    const int mBase = blockIdx.x * BM;

    float acc[4][4][4];
    #pragma unroll
    for (int i = 0; i < 4; ++i)
        #pragma unroll
        for (int j = 0; j < 4; ++j)
            #pragma unroll
            for (int r = 0; r < 4; ++r) acc[i][j][r] = 0.f;

    for (int kb = 0; kb < KT; kb += BK) {
        #pragma unroll
        for (int it = 0; it < 4; ++it) {
            int j   = tid + it * 256;
            int row = j >> 3;
            int kq  = (j & 7) * 4;
            int gr  = mBase + row;
            float4 v = make_float4(0.f, 0.f, 0.f, 0.f);
            if (gr < NN) v = __ldg((const float4*)&A1[(size_t)gr * D + kb + kq]);
            uint4 w;
            w.x = f2tf32(v.x); w.y = f2tf32(v.y); w.z = f2tf32(v.z); w.w = f2tf32(v.w);
            *(uint4*)&As[row][kq] = w;
        }
        #pragma unroll
        for (int it = 0; it < 4; ++it) {
            int j  = tid + it * 256;
            int kr = j >> 5;
            int nq = (j & 31) * 4;
            float4 v = __ldg((const float4*)&WT[(size_t)(kb + kr) * BN + nq]);
            uint4 w;
            w.x = f2tf32(v.x); w.y = f2tf32(v.y); w.z = f2tf32(v.z); w.w = f2tf32(v.w);
            *(uint4*)&Ws[kr][nq] = w;
        }
        __syncthreads();

        #pragma unroll
        for (int ks = 0; ks < BK / 8; ++ks) {
            uint32_t a[4][4], b[4][2];
            #pragma unroll
            for (int i = 0; i < 4; ++i) {
                int m = rowBase + i * 16 + gidq;
                int k = ks * 8 + tg;
                a[i][0] = As[m][k];
                a[i][1] = As[m + 8][k];
                a[i][2] = As[m][k + 4];
                a[i][3] = As[m + 8][k + 4];
            }
            #pragma unroll
            for (int j = 0; j < 4; ++j) {
                int n = colBase + j * 8 + gidq;
                int k = ks * 8 + tg;
                b[j][0] = Ws[k][n];
                b[j][1] = Ws[k + 4][n];
            }
            #pragma unroll
            for (int i = 0; i < 4; ++i)
                #pragma unroll
                for (int j = 0; j < 4; ++j)
                    asm volatile(
                        "mma.sync.aligned.m16n8k8.row.col.f32.tf32.tf32.f32 "
                        "{%0,%1,%2,%3}, {%4,%5,%6,%7}, {%8,%9}, {%0,%1,%2,%3};"
                        : "+f"(acc[i][j][0]), "+f"(acc[i][j][1]),
                          "+f"(acc[i][j][2]), "+f"(acc[i][j][3])
                        : "r"(a[i][0]), "r"(a[i][1]), "r"(a[i][2]), "r"(a[i][3]),
                          "r"(b[j][0]), "r"(b[j][1]));
        }
        __syncthreads();
    }

    // ---- epilogue ----
    if constexpr (MODE == 0) {
        float2 bs[4];
        #pragma unroll
        for (int j = 0; j < 4; ++j) {
            int col = colBase + j * 8 + 2 * tg;
            bs[j].x = __ldg(&bias[col]);
            bs[j].y = __ldg(&bias[col + 1]);
        }
        #pragma unroll
        for (int i = 0; i < 4; ++i)
            #pragma unroll
            for (int half = 0; half < 2; ++half) {
                int r = mBase + rowBase + i * 16 + gidq + half * 8;
                if (r >= NN) continue;
                #pragma unroll
                for (int j = 0; j < 4; ++j) {
                    int col = colBase + j * 8 + 2 * tg;
                    *(float2*)&out1[(size_t)r * D + col] =
                        make_float2(acc[i][j][half * 2 + 0] + bs[j].x,
                                    acc[i][j][half * 2 + 1] + bs[j].y);
                }
            }
    } else if constexpr (MODE == 1) {
        #pragma unroll
        for (int i = 0; i < 4; ++i)
            #pragma unroll
            for (int half = 0; half < 2; ++half) {
                int r = mBase + rowBase + i * 16 + gidq + half * 8;
                if (r >= NN) continue;
                #pragma unroll
                for (int j = 0; j < 4; ++j) {
                    int col = colBase + j * 8 + 2 * tg;
                    float2 ss = *(const float2*)&S[(size_t)r * D + col];
                    float2 uu = *(const float2*)&u[(size_t)r * D + col];
                    float2 o;
                    o.x = fmaxf(acc[i][j][half * 2 + 0] + ss.x, 0.f) * ((uu.x >= PDROP) ? INV_KEEP : 0.f);
                    o.y = fmaxf(acc[i][j][half * 2 + 1] + ss.y, 0.f) * ((uu.y >= PDROP) ? INV_KEEP : 0.f);
                    *(float2*)&out1[(size_t)r * D + col] = o;
                }
            }
    } else {
        const bool isY = (colBase < 64);
        float2 bs[4];
        #pragma unroll
        for (int j = 0; j < 4; ++j) {
            if (!isY) {
                int col = colBase - 64 + j * 8 + 2 * tg;
                bs[j].x = __ldg(&bias[col]);
                bs[j].y = __ldg(&bias[col + 1]);
            } else {
                bs[j].x = bs[j].y = 0.f;
            }
        }
        #pragma unroll
        for (int i = 0; i < 4; ++i)
            #pragma unroll
            for (int half = 0; half < 2; ++half) {
                int r = mBase + rowBase + i * 16 + gidq + half * 8;
                if (r >= NN) continue;
                #pragma unroll
                for (int j = 0; j < 4; ++j) {
                    float c0 = acc[i][j][half * 2 + 0];
                    float c1 = acc[i][j][half * 2 + 1];
                    if (isY) {
                        int col = colBase + j * 8 + 2 * tg;
                        *(float2*)&out1[(size_t)r * DO + col] = make_float2(c0, c1);
                    } else {
                        int col = colBase - 64 + j * 8 + 2 * tg;
                        *(float2*)&out2[(size_t)r * DO + col] =
                            make_float2(c0 + bs[j].x, c1 + bs[j].y);
                    }
                }
            }
    }
}

// ---------------------------------------------------------------------------
extern "C" void kernel_launch(void* const* d_in, const int* in_sizes, int n_in,
                              void* d_out, int out_size) {
    const float* x   = (const float*)d_in[0];
    const float* u1  = (const float*)d_in[1];
    const float* u2  = (const float*)d_in[2];
    const float* wl0 = (const float*)d_in[3];
    const float* bl0 = (const float*)d_in[4];
    const float* wr0 = (const float*)d_in[5];
    const float* wl1 = (const float*)d_in[6];
    const float* bl1 = (const float*)d_in[7];
    const float* wr1 = (const float*)d_in[8];
    const float* wl2 = (const float*)d_in[9];
    const float* bl2 = (const float*)d_in[10];
    const float* wr2 = (const float*)d_in[11];
    const int*   ei  = (const int*)d_in[12];
    float* out = (float*)d_out;

    float *agg, *s, *h0, *h1, *y, *wT;
    cudaGetSymbolAddress((void**)&agg, g_agg);
    cudaGetSymbolAddress((void**)&s,   g_s);
    cudaGetSymbolAddress((void**)&h0,  g_h0);
    cudaGetSymbolAddress((void**)&h1,  g_h1);
    cudaGetSymbolAddress((void**)&y,   g_y);
    cudaGetSymbolAddress((void**)&wT,  g_wT);

    // side stream + events, created once (resource setup only; work is
    // identical on every call)
    static cudaStream_t sB = nullptr;
    static cudaEvent_t evFork, evCSR, evH0, evS1;
    if (sB == nullptr) {
        cudaStreamCreateWithFlags(&sB, cudaStreamNonBlocking);
        cudaEventCreateWithFlags(&evFork, cudaEventDisableTiming);
        cudaEventCreateWithFlags(&evCSR,  cudaEventDisableTiming);
        cudaEventCreateWithFlags(&evH0,   cudaEventDisableTiming);
        cudaEventCreateWithFlags(&evS1,   cudaEventDisableTiming);
    }

    const int gemmBlocks = (NN + 127) / 128;   // 391

    // ---- fork: CSR build on sB, weights + layer-0 self GEMM on stream 0 ----
    cudaEventRecord(evFork, 0);
    cudaStreamWaitEvent(sB, evFork, 0);

    zero_deg<<<(NN + 255) / 256, 256, 0, sB>>>();
    deg_kernel<<<EE / 256, 256, 0, sB>>>(ei);
    scan_s1<<<SCAN_NBLK, SCAN_B, 0, sB>>>();
    scan_s2<<<1, 256, 0, sB>>>();
    scan_s3<<<SCAN_NBLK, SCAN_B, 0, sB>>>();
    fill_kernel<<<EE / 256, 256, 0, sB>>>(ei);
    cudaEventRecord(evCSR, sB);

    prep_weights<<<(5 * D * D + 255) / 256, 256>>>(wl0, wr0, wl1, wr1, wl2, wr2);
    gemm_tf32<0><<<gemmBlocks, 256>>>(x, wT + 1 * D * D, bl0, nullptr, nullptr, s, nullptr);

    // ---- layer 0: pull (needs CSR) then mean GEMM ----
    cudaStreamWaitEvent(0, evCSR, 0);
    pull128_kernel<<<(NN * 32) / 256, 256>>>((const float4*)x, (float4*)agg);
    gemm_tf32<1><<<gemmBlocks, 256>>>(agg, wT + 0 * D * D, nullptr, s, u1, h0, nullptr);

    // ---- layer 1: self GEMM on sB overlaps pull on stream 0 ----
    cudaEventRecord(evH0, 0);
    cudaStreamWaitEvent(sB, evH0, 0);
    gemm_tf32<0><<<gemmBlocks, 256, 0, sB>>>(h0, wT + 3 * D * D, bl1, nullptr, nullptr, s, nullptr);
    cudaEventRecord(evS1, sB);

    pull128_kernel<<<(NN * 32) / 256, 256>>>((const float4*)h0, (float4*)agg);
    cudaStreamWaitEvent(0, evS1, 0);
    gemm_tf32<1><<<gemmBlocks, 256>>>(agg, wT + 2 * D * D, nullptr, s, u2, h1, nullptr);

    // ---- layer 2: transform first (y + residual), then 64-d pull-add ----
    gemm_tf32<2><<<gemmBlocks, 256>>>(h1, wT + 4 * D * D, bl2, nullptr, nullptr, y, out);
    pull64_add_kernel<<<(NN * 16) / 256, 256>>>((const float4*)y, (float4*)out);
}

// round 9
// speedup vs baseline: 1.2261x; 1.2261x over previous
#include <cuda_runtime.h>
#include <cuda_fp16.h>
#include <cstdint>

// ---------------------------------------------------------------------------
// GraphSAGE on GB300, round 9: full fp16 storage + m16n8k16 fp16 tensor MMA
// (fp16 mantissa == tf32 mantissa; all accumulation fp32 -> same error class,
//  half the memory traffic, 2x the tensor throughput).
//  - CSR pull-mode mean aggregation (fp16 gather, fp32 accumulate)
//  - fused K=256 GEMM per layer: [mean | h] @ [wl | wr]^T + bias, relu, dropout
//  - layer-2 linearity trick (transform to 64-d first, then aggregate)
//  - CSR build forked onto side stream, overlapped with x-convert + weight prep
// ---------------------------------------------------------------------------

constexpr int   NN   = 50000;
constexpr int   EE   = 800000;
constexpr int   D    = 128;
constexpr int   DO   = 64;
constexpr float PDROP = 0.3f;
constexpr float INV_KEEP = 1.0f / 0.7f;

constexpr int SCAN_B = 256;
constexpr int SCAN_NBLK = (NN + SCAN_B - 1) / SCAN_B;   // 196

// packed weight segments (half2 granularity = uint32): [n][kpair]
constexpr int WP_L0 = 0;             // 128 n x 128 pairs (wl0|wr0)
constexpr int WP_L1 = 16384;         // 128 n x 128 pairs (wl1|wr1)
constexpr int WP_L2 = 32768;         // 128 n x  64 pairs (wl2 rows 0-63, wr2 rows 64-127)
constexpr int WP_TOT = 40960;

// ---- scratch (static device globals) ----
__device__ __align__(256) __half   g_xh [NN * D];
__device__ __align__(256) __half   g_h0 [NN * D];
__device__ __align__(256) __half   g_h1 [NN * D];
__device__ __align__(256) __half   g_agg[NN * D];
__device__ __align__(256) __half   g_y  [NN * DO];
__device__ __align__(256) uint32_t g_wPk[WP_TOT];
__device__ __align__(256) int      g_deg[NN];
__device__ __align__(256) int      g_rowptr[NN + 1];
__device__ __align__(256) int      g_cursor[NN];
__device__ __align__(256) int      g_adj[EE];
__device__ __align__(256) int      g_blksum[SCAN_NBLK + 1];

// ---------------------------------------------------------------------------
// x -> fp16 (8 floats per thread)
// ---------------------------------------------------------------------------
__global__ void convert_x(const float4* __restrict__ x, uint4* __restrict__ xh) {
    int i = blockIdx.x * blockDim.x + threadIdx.x;
    if (i >= NN * D / 8) return;
    float4 a = __ldg(&x[2 * i]);
    float4 b = __ldg(&x[2 * i + 1]);
    __half2 h0 = __floats2half2_rn(a.x, a.y);
    __half2 h1 = __floats2half2_rn(a.z, a.w);
    __half2 h2 = __floats2half2_rn(b.x, b.y);
    __half2 h3 = __floats2half2_rn(b.z, b.w);
    uint4 o;
    o.x = *(uint32_t*)&h0; o.y = *(uint32_t*)&h1;
    o.z = *(uint32_t*)&h2; o.w = *(uint32_t*)&h3;
    xh[i] = o;
}

// ---------------------------------------------------------------------------
// weights -> packed fp16 half2 [n][kpair]
// ---------------------------------------------------------------------------
__global__ void prep_weights(const float* __restrict__ wl0, const float* __restrict__ wr0,
                             const float* __restrict__ wl1, const float* __restrict__ wr1,
                             const float* __restrict__ wl2, const float* __restrict__ wr2) {
    int idx = blockIdx.x * blockDim.x + threadIdx.x;
    if (idx >= WP_TOT) return;
    float v0, v1;
    if (idx < WP_L2) {                       // layers 0/1: K=256 fused (wl | wr)
        const float* wl = (idx < WP_L1) ? wl0 : wl1;
        const float* wr = (idx < WP_L1) ? wr0 : wr1;
        int r = idx & 16383;
        int n = r >> 7;            // 0..127
        int p = r & 127;           // pair 0..127 -> k = 2p, 2p+1
        int k0 = 2 * p;
        v0 = (k0 < 128)     ? wl[n * D + k0]       : wr[n * D + k0 - 128];
        v1 = (k0 + 1 < 128) ? wl[n * D + k0 + 1]   : wr[n * D + k0 + 1 - 128];
    } else {                                 // layer 2: K=128; n<64 -> wl2, else wr2
        int r = idx - WP_L2;
        int n = r >> 6;            // 0..127
        int p = r & 63;            // pair 0..63
        int k0 = 2 * p;
        if (n < DO) { v0 = wl2[n * D + k0]; v1 = wl2[n * D + k0 + 1]; }
        else        { v0 = wr2[(n - DO) * D + k0]; v1 = wr2[(n - DO) * D + k0 + 1]; }
    }
    __half2 h = __floats2half2_rn(v0, v1);
    g_wPk[idx] = *(uint32_t*)&h;
}

// ---------------------------------------------------------------------------
// CSR build
// ---------------------------------------------------------------------------
__global__ void zero_deg() {
    int i = blockIdx.x * blockDim.x + threadIdx.x;
    if (i < NN) g_deg[i] = 0;
}

__global__ void deg_kernel(const int* __restrict__ ei) {
    int e = blockIdx.x * blockDim.x + threadIdx.x;
    if (e < EE) atomicAdd(&g_deg[ei[EE + e]], 1);
}

__global__ void scan_s1() {
    __shared__ int sh[SCAN_B];
    int idx = blockIdx.x * SCAN_B + threadIdx.x;
    int v = (idx < NN) ? g_deg[idx] : 0;
    sh[threadIdx.x] = v;
    __syncthreads();
    for (int off = SCAN_B / 2; off > 0; off >>= 1) {
        if (threadIdx.x < off) sh[threadIdx.x] += sh[threadIdx.x + off];
        __syncthreads();
    }
    if (threadIdx.x == 0) g_blksum[blockIdx.x] = sh[0];
}

__global__ void scan_s2() {
    __shared__ int sh[SCAN_NBLK];
    int t = threadIdx.x;
    if (t < SCAN_NBLK) sh[t] = g_blksum[t];
    __syncthreads();
    for (int off = 1; off < SCAN_NBLK; off <<= 1) {
        int v = 0;
        if (t < SCAN_NBLK && t >= off) v = sh[t - off];
        __syncthreads();
        if (t < SCAN_NBLK && t >= off) sh[t] += v;
        __syncthreads();
    }
    if (t < SCAN_NBLK) g_blksum[t] = (t > 0) ? sh[t - 1] : 0;
    if (t == SCAN_NBLK - 1) g_rowptr[NN] = sh[SCAN_NBLK - 1];
}

__global__ void scan_s3() {
    __shared__ int sh[SCAN_B];
    int idx = blockIdx.x * SCAN_B + threadIdx.x;
    int t = threadIdx.x;
    int v = (idx < NN) ? g_deg[idx] : 0;
    sh[t] = v;
    __syncthreads();
    for (int off = 1; off < SCAN_B; off <<= 1) {
        int p = 0;
        if (t >= off) p = sh[t - off];
        __syncthreads();
        if (t >= off) sh[t] += p;
        __syncthreads();
    }
    if (idx < NN) {
        int ex = sh[t] - v + g_blksum[blockIdx.x];
        g_rowptr[idx] = ex;
        g_cursor[idx] = ex;
    }
}

__global__ void fill_kernel(const int* __restrict__ ei) {
    int e = blockIdx.x * blockDim.x + threadIdx.x;
    if (e < EE) {
        int d = ei[EE + e];
        int pos = atomicAdd(&g_cursor[d], 1);
        g_adj[pos] = ei[e];
    }
}

// ---------------------------------------------------------------------------
// Pull-mode mean, fp16 features (fp32 accumulate).
// 128-d: one warp per node, 4 halves (uint2) per lane.
// ---------------------------------------------------------------------------
__global__ void pull128h(const uint2* __restrict__ feat, uint2* __restrict__ out) {
    int warp = (blockIdx.x * blockDim.x + threadIdx.x) >> 5;
    int lane = threadIdx.x & 31;
    if (warp >= NN) return;
    int beg = g_rowptr[warp], end = g_rowptr[warp + 1];
    float4 a0 = make_float4(0.f, 0.f, 0.f, 0.f);
    float4 a1 = make_float4(0.f, 0.f, 0.f, 0.f);
    for (int eb = beg; eb < end; eb += 32) {
        int n = end - eb;
        int myAdj = (lane < n) ? __ldg(&g_adj[eb + lane]) : 0;
        int lim = min(n, 32);
        int t = 0;
        for (; t + 2 <= lim; t += 2) {
            int s0 = __shfl_sync(0xffffffffu, myAdj, t);
            int s1 = __shfl_sync(0xffffffffu, myAdj, t + 1);
            uint2 v0 = __ldg(&feat[(size_t)s0 * 32 + lane]);
            uint2 v1 = __ldg(&feat[(size_t)s1 * 32 + lane]);
            float2 f0 = __half22float2(*(__half2*)&v0.x);
            float2 f1 = __half22float2(*(__half2*)&v0.y);
            float2 g0 = __half22float2(*(__half2*)&v1.x);
            float2 g1 = __half22float2(*(__half2*)&v1.y);
            a0.x += f0.x; a0.y += f0.y; a0.z += f1.x; a0.w += f1.y;
            a1.x += g0.x; a1.y += g0.y; a1.z += g1.x; a1.w += g1.y;
        }
        if (t < lim) {
            int s0 = __shfl_sync(0xffffffffu, myAdj, t);
            uint2 v0 = __ldg(&feat[(size_t)s0 * 32 + lane]);
            float2 f0 = __half22float2(*(__half2*)&v0.x);
            float2 f1 = __half22float2(*(__half2*)&v0.y);
            a0.x += f0.x; a0.y += f0.y; a0.z += f1.x; a0.w += f1.y;
        }
    }
    float sc = 1.0f / fmaxf((float)(end - beg), 1.0f);
    __half2 o0 = __floats2half2_rn((a0.x + a1.x) * sc, (a0.y + a1.y) * sc);
    __half2 o1 = __floats2half2_rn((a0.z + a1.z) * sc, (a0.w + a1.w) * sc);
    uint2 o;
    o.x = *(uint32_t*)&o0; o.y = *(uint32_t*)&o1;
    out[(size_t)warp * 32 + lane] = o;
}

// 64-d pull + add into fp32 out. Half-warp per node, 4 halves per lane.
__global__ void pull64h_add(const uint2* __restrict__ feat, float4* __restrict__ out) {
    int gid = blockIdx.x * blockDim.x + threadIdx.x;
    int node = gid >> 4;
    int c = gid & 15;
    if (node >= NN) return;
    int beg = g_rowptr[node], end = g_rowptr[node + 1];
    float4 a0 = make_float4(0.f, 0.f, 0.f, 0.f);
    float4 a1 = make_float4(0.f, 0.f, 0.f, 0.f);
    for (int eb = beg; eb < end; eb += 16) {
        int n = end - eb;
        int myAdj = (c < n) ? __ldg(&g_adj[eb + c]) : 0;
        int lim = min(n, 16);
        int t = 0;
        for (; t + 2 <= lim; t += 2) {
            int s0 = __shfl_sync(0xffffffffu, myAdj, t, 16);
            int s1 = __shfl_sync(0xffffffffu, myAdj, t + 1, 16);
            uint2 v0 = __ldg(&feat[(size_t)s0 * 16 + c]);
            uint2 v1 = __ldg(&feat[(size_t)s1 * 16 + c]);
            float2 f0 = __half22float2(*(__half2*)&v0.x);
            float2 f1 = __half22float2(*(__half2*)&v0.y);
            float2 g0 = __half22float2(*(__half2*)&v1.x);
            float2 g1 = __half22float2(*(__half2*)&v1.y);
            a0.x += f0.x; a0.y += f0.y; a0.z += f1.x; a0.w += f1.y;
            a1.x += g0.x; a1.y += g0.y; a1.z += g1.x; a1.w += g1.y;
        }
        if (t < lim) {
            int s0 = __shfl_sync(0xffffffffu, myAdj, t, 16);
            uint2 v0 = __ldg(&feat[(size_t)s0 * 16 + c]);
            float2 f0 = __half22float2(*(__half2*)&v0.x);
            float2 f1 = __half22float2(*(__half2*)&v0.y);
            a0.x += f0.x; a0.y += f0.y; a0.z += f1.x; a0.w += f1.y;
        }
    }
    float sc = 1.0f / fmaxf((float)(end - beg), 1.0f);
    float4 o = out[(size_t)node * 16 + c];
    o.x += (a0.x + a1.x) * sc; o.y += (a0.y + a1.y) * sc;
    o.z += (a0.z + a1.z) * sc; o.w += (a0.w + a1.w) * sc;
    out[(size_t)node * 16 + c] = o;
}

// ---------------------------------------------------------------------------
// fp16 tensor-core GEMM (m16n8k16, fp32 accumulate).
// MODE 0: out_h = relu( [A1 | A2](fp16, K=256) @ Wpk + bias ) * dropout(u)
// MODE 1: K=128; cols 0..63 -> y(fp16) = A1 @ wl2^T ; cols 64..127 -> out(fp32) = A1 @ wr2^T + bias
// BM=BN=128, BK=32; 8 warps, warp tile 64x32.
// A frags via ldmatrix.x4 from 80B-strided tile (conflict-free);
// B frags from half2-packed [n][kpair] tile, stride 20 words (conflict-free).
// ---------------------------------------------------------------------------
template <int MODE>
__launch_bounds__(256)
__global__ void gemm_h(const __half* __restrict__ A1, const __half* __restrict__ A2,
                       const uint32_t* __restrict__ Wpk, const float* __restrict__ bias,
                       const float* __restrict__ u,
                       __half* __restrict__ outh, float* __restrict__ outf) {
    constexpr int BM = 128, BK = 32;
    constexpr int KT = (MODE == 0) ? 256 : 128;
    constexpr int PP = (MODE == 0) ? 128 : 64;     // global pairs per n row
    __shared__ __half   As[BM][40];                // 32 data + 8 pad (80 B stride)
    __shared__ uint32_t Ws[128][20];               // 16 data + 4 pad words

    const int tid  = threadIdx.x;
    const int wid  = tid >> 5;
    const int lane = tid & 31;
    const int gidq = lane >> 2;
    const int tg   = lane & 3;
    const int rowBase = (wid >> 2) * 64;
    const int colBase = (wid & 3) * 32;
    const int mBase = blockIdx.x * BM;

    const uint32_t asBase = (uint32_t)__cvta_generic_to_shared(&As[0][0]);
    const int lr = lane & 15;        // ldmatrix row within 16
    const int lc = lane >> 4;        // 0/1 -> k halves 0-7 / 8-15

    float acc[4][4][4];
    #pragma unroll
    for (int i = 0; i < 4; ++i)
        #pragma unroll
        for (int j = 0; j < 4; ++j)
            #pragma unroll
            for (int r = 0; r < 4; ++r) acc[i][j][r] = 0.f;

    for (int kb = 0; kb < KT; kb += BK) {
        const __half* A = A1;
        int ko = kb;
        if constexpr (MODE == 0) {
            if (kb >= 128) { A = A2; ko = kb - 128; }
        }
        // A tile: 128 rows x 32 halves; uint4 = 8 halves; 512 loads over 256 thr x2
        #pragma unroll
        for (int it = 0; it < 2; ++it) {
            int j   = tid + it * 256;
            int row = j >> 2;
            int s   = (j & 3) * 8;                 // half offset 0,8,16,24
            int gr  = mBase + row;
            uint4 v = make_uint4(0, 0, 0, 0);
            if (gr < NN) v = __ldg((const uint4*)&A[(size_t)gr * D + ko + s]);
            *(uint4*)&As[row][s] = v;
        }
        // W tile: 128 n x 16 pairs; uint4 = 4 pairs; 512 loads over 256 thr x2
        #pragma unroll
        for (int it = 0; it < 2; ++it) {
            int j = tid + it * 256;
            int n = j >> 2;
            int q = (j & 3) * 4;                   // pair offset 0,4,8,12
            uint4 v = __ldg((const uint4*)&Wpk[(size_t)n * PP + (kb >> 1) + q]);
            *(uint4*)&Ws[n][q] = v;
        }
        __syncthreads();

        #pragma unroll
        for (int ks = 0; ks < 2; ++ks) {           // two k16 chunks per BK=32
            uint32_t a[4][4], b[4][2];
            #pragma unroll
            for (int i = 0; i < 4; ++i) {
                int row = rowBase + i * 16 + lr;
                uint32_t addr = asBase + (uint32_t)((row * 40 + ks * 16 + lc * 8) * 2);
                asm volatile("ldmatrix.sync.aligned.m8n8.x4.shared.b16 {%0,%1,%2,%3}, [%4];"
                             : "=r"(a[i][0]), "=r"(a[i][1]), "=r"(a[i][2]), "=r"(a[i][3])
                             : "r"(addr));
            }
            #pragma unroll
            for (int j = 0; j < 4; ++j) {
                int n = colBase + j * 8 + gidq;
                b[j][0] = Ws[n][8 * ks + tg];
                b[j][1] = Ws[n][8 * ks + tg + 4];
            }
            #pragma unroll
            for (int i = 0; i < 4; ++i)
                #pragma unroll
                for (int j = 0; j < 4; ++j)
                    asm volatile(
                        "mma.sync.aligned.m16n8k16.row.col.f32.f16.f16.f32 "
                        "{%0,%1,%2,%3}, {%4,%5,%6,%7}, {%8,%9}, {%0,%1,%2,%3};"
                        : "+f"(acc[i][j][0]), "+f"(acc[i][j][1]),
                          "+f"(acc[i][j][2]), "+f"(acc[i][j][3])
                        : "r"(a[i][0]), "r"(a[i][1]), "r"(a[i][2]), "r"(a[i][3]),
                          "r"(b[j][0]), "r"(b[j][1]));
        }
        __syncthreads();
    }

    // ---- epilogue ----
    if constexpr (MODE == 0) {
        float2 bs[4];
        #pragma unroll
        for (int j = 0; j < 4; ++j) {
            int col = colBase + j * 8 + 2 * tg;
            bs[j].x = __ldg(&bias[col]);
            bs[j].y = __ldg(&bias[col + 1]);
        }
        #pragma unroll
        for (int i = 0; i < 4; ++i)
            #pragma unroll
            for (int half = 0; half < 2; ++half) {
                int r = mBase + rowBase + i * 16 + gidq + half * 8;
                if (r >= NN) continue;
                #pragma unroll
                for (int j = 0; j < 4; ++j) {
                    int col = colBase + j * 8 + 2 * tg;
                    float2 uu = *(const float2*)&u[(size_t)r * D + col];
                    float ox = fmaxf(acc[i][j][half * 2 + 0] + bs[j].x, 0.f) * ((uu.x >= PDROP) ? INV_KEEP : 0.f);
                    float oy = fmaxf(acc[i][j][half * 2 + 1] + bs[j].y, 0.f) * ((uu.y >= PDROP) ? INV_KEEP : 0.f);
                    __half2 oh = __floats2half2_rn(ox, oy);
                    *(uint32_t*)&outh[(size_t)r * D + col] = *(uint32_t*)&oh;
                }
            }
    } else {
        const bool isY = (colBase < 64);
        float2 bs[4];
        #pragma unroll
        for (int j = 0; j < 4; ++j) {
            if (!isY) {
                int col = colBase - 64 + j * 8 + 2 * tg;
                bs[j].x = __ldg(&bias[col]);
                bs[j].y = __ldg(&bias[col + 1]);
            } else {
                bs[j].x = bs[j].y = 0.f;
            }
        }
        #pragma unroll
        for (int i = 0; i < 4; ++i)
            #pragma unroll
            for (int half = 0; half < 2; ++half) {
                int r = mBase + rowBase + i * 16 + gidq + half * 8;
                if (r >= NN) continue;
                #pragma unroll
                for (int j = 0; j < 4; ++j) {
                    float c0 = acc[i][j][half * 2 + 0];
                    float c1 = acc[i][j][half * 2 + 1];
                    if (isY) {
                        int col = colBase + j * 8 + 2 * tg;
                        __half2 oh = __floats2half2_rn(c0, c1);
                        *(uint32_t*)&outh[(size_t)r * DO + col] = *(uint32_t*)&oh;
                    } else {
                        int col = colBase - 64 + j * 8 + 2 * tg;
                        *(float2*)&outf[(size_t)r * DO + col] =
                            make_float2(c0 + bs[j].x, c1 + bs[j].y);
                    }
                }
            }
    }
}

// ---------------------------------------------------------------------------
extern "C" void kernel_launch(void* const* d_in, const int* in_sizes, int n_in,
                              void* d_out, int out_size) {
    const float* x   = (const float*)d_in[0];
    const float* u1  = (const float*)d_in[1];
    const float* u2  = (const float*)d_in[2];
    const float* wl0 = (const float*)d_in[3];
    const float* bl0 = (const float*)d_in[4];
    const float* wr0 = (const float*)d_in[5];
    const float* wl1 = (const float*)d_in[6];
    const float* bl1 = (const float*)d_in[7];
    const float* wr1 = (const float*)d_in[8];
    const float* wl2 = (const float*)d_in[9];
    const float* bl2 = (const float*)d_in[10];
    const float* wr2 = (const float*)d_in[11];
    const int*   ei  = (const int*)d_in[12];
    float* out = (float*)d_out;

    __half *xh, *h0, *h1, *agg, *y;
    uint32_t* wPk;
    cudaGetSymbolAddress((void**)&xh,  g_xh);
    cudaGetSymbolAddress((void**)&h0,  g_h0);
    cudaGetSymbolAddress((void**)&h1,  g_h1);
    cudaGetSymbolAddress((void**)&agg, g_agg);
    cudaGetSymbolAddress((void**)&y,   g_y);
    cudaGetSymbolAddress((void**)&wPk, g_wPk);

    static cudaStream_t sB = nullptr;
    static cudaEvent_t evFork, evCSR;
    if (sB == nullptr) {
        cudaStreamCreateWithFlags(&sB, cudaStreamNonBlocking);
        cudaEventCreateWithFlags(&evFork, cudaEventDisableTiming);
        cudaEventCreateWithFlags(&evCSR,  cudaEventDisableTiming);
    }

    const int gemmBlocks = (NN + 127) / 128;   // 391

    // ---- fork: CSR build on sB; x-convert + weight prep on stream 0 ----
    cudaEventRecord(evFork, 0);
    cudaStreamWaitEvent(sB, evFork, 0);

    zero_deg<<<(NN + 255) / 256, 256, 0, sB>>>();
    deg_kernel<<<EE / 256, 256, 0, sB>>>(ei);
    scan_s1<<<SCAN_NBLK, SCAN_B, 0, sB>>>();
    scan_s2<<<1, 256, 0, sB>>>();
    scan_s3<<<SCAN_NBLK, SCAN_B, 0, sB>>>();
    fill_kernel<<<EE / 256, 256, 0, sB>>>(ei);
    cudaEventRecord(evCSR, sB);

    convert_x<<<(NN * D / 8 + 255) / 256, 256>>>((const float4*)x, (uint4*)xh);
    prep_weights<<<(WP_TOT + 255) / 256, 256>>>(wl0, wr0, wl1, wr1, wl2, wr2);
    cudaStreamWaitEvent(0, evCSR, 0);

    // layer 0
    pull128h<<<(NN * 32) / 256, 256>>>((const uint2*)xh, (uint2*)agg);
    gemm_h<0><<<gemmBlocks, 256>>>(agg, xh, wPk + WP_L0, bl0, u1, h0, nullptr);

    // layer 1
    pull128h<<<(NN * 32) / 256, 256>>>((const uint2*)h0, (uint2*)agg);
    gemm_h<0><<<gemmBlocks, 256>>>(agg, h0, wPk + WP_L1, bl1, u2, h1, nullptr);

    // layer 2: transform first (y fp16 + residual fp32), then 64-d pull-add
    gemm_h<1><<<gemmBlocks, 256>>>(h1, nullptr, wPk + WP_L2, bl2, nullptr, y, out);
    pull64h_add<<<(NN * 16) / 256, 256>>>((const uint2*)y, (float4*)out);
}